// round 8
// baseline (speedup 1.0000x reference)
#include <cuda_runtime.h>
#include <cstdint>
#include <cstddef>

#define BB 8
#define NN 2048
#define HE 4
#define HD 32

// ---------------- device scratch (no allocations allowed) ----------------
__device__ float    g_Wh[BB * NN * 128];            // 8 MB   [b*N+n][128]
__device__ float4   g_ip[BB * NN * HE];             // 1 MB   {-s, e^s, e^{0.2s}, 0}
__device__ float4   g_jp[BB * NN * HE];             // 1 MB   { t, e^t, e^{0.2t}, 0}
__device__ unsigned g_Ab[BB * NN * (NN / 32)];      // 4 MB   packed adjacency bits

// ---------------- K1: Wh = h @ W  (16384x128 @ 128x128) ----------------
__global__ __launch_bounds__(256) void k_mm(const float* __restrict__ hmat,
                                            const float* __restrict__ W) {
    __shared__ float hs[64 * 36];     // 64 rows x 32 k, padded row stride 36
    __shared__ float Ws[32 * 128];
    int tid = threadIdx.x;
    int tx = tid & 15, ty = tid >> 4;
    int rbase = blockIdx.x * 64;

    float acc[4][8];
#pragma unroll
    for (int i = 0; i < 4; ++i)
#pragma unroll
        for (int j = 0; j < 8; ++j) acc[i][j] = 0.f;

    for (int k0 = 0; k0 < 128; k0 += 32) {
        __syncthreads();
#pragma unroll
        for (int m = 0; m < 2; ++m) {
            int idx = tid * 2 + m;
            int r = idx >> 3, q = idx & 7;
            *(float4*)(hs + r * 36 + q * 4) =
                *(const float4*)(hmat + (size_t)(rbase + r) * 128 + k0 + q * 4);
        }
#pragma unroll
        for (int m = 0; m < 4; ++m) {
            int idx = tid + 256 * m;
            int kk = idx >> 5, c4 = idx & 31;
            *(float4*)(Ws + kk * 128 + c4 * 4) =
                *(const float4*)(W + (size_t)(k0 + kk) * 128 + c4 * 4);
        }
        __syncthreads();
#pragma unroll
        for (int kk = 0; kk < 32; ++kk) {
            float av[4], bv[8];
#pragma unroll
            for (int i = 0; i < 4; ++i) av[i] = hs[(ty * 4 + i) * 36 + kk];
#pragma unroll
            for (int j = 0; j < 8; ++j) bv[j] = Ws[kk * 128 + tx + 16 * j];
#pragma unroll
            for (int i = 0; i < 4; ++i)
#pragma unroll
                for (int j = 0; j < 8; ++j) acc[i][j] += av[i] * bv[j];
        }
    }
#pragma unroll
    for (int i = 0; i < 4; ++i)
#pragma unroll
        for (int j = 0; j < 8; ++j)
            g_Wh[(size_t)(rbase + ty * 4 + i) * 128 + tx + 16 * j] = acc[i][j];
}

// ---------------- K2: per-(node,head) attention params -------------------
// s = Wh_head . a[:32], t = Wh_head . a[32:]
// exp(leakyrelu(s_i+t_j)) = (s+t>0) ? e^s e^t : e^{0.2s} e^{0.2t}
__global__ __launch_bounds__(256) void k_params(const float* __restrict__ a) {
    __shared__ float sa[64];
    int tid = threadIdx.x;
    if (tid < 64) sa[tid] = a[tid];
    __syncthreads();
    int idx = blockIdx.x * 256 + tid;           // = (b*N+n)*4 + h
    int nh = idx >> 2, hh = idx & 3;
    const float4* wh = (const float4*)(g_Wh + (size_t)nh * 128 + hh * 32);
    float s = 0.f, t = 0.f;
#pragma unroll
    for (int k = 0; k < 8; ++k) {
        float4 w = wh[k];
        s += w.x * sa[4 * k + 0] + w.y * sa[4 * k + 1] + w.z * sa[4 * k + 2] + w.w * sa[4 * k + 3];
        t += w.x * sa[32 + 4 * k + 0] + w.y * sa[32 + 4 * k + 1] + w.z * sa[32 + 4 * k + 2] + w.w * sa[32 + 4 * k + 3];
    }
    g_ip[idx] = make_float4(-s, expf(s), expf(0.2f * s), 0.f);
    g_jp[idx] = make_float4(t, expf(t), expf(0.2f * t), 0.f);
}

// ---------------- K3: pack A into bitmasks (134MB -> 4.2MB) --------------
// One warp packs 1024 consecutive ints into 32 bitmask words.
// Need B*N*N/1024 = 32768 warps = 1,048,576 threads = 4096 blocks of 256.
__global__ __launch_bounds__(256) void k_pack(const int* __restrict__ A) {
    int gt = blockIdx.x * 256 + threadIdx.x;
    int warpId = gt >> 5, lane = gt & 31;
    const int* src = A + (size_t)warpId * 1024;
    unsigned keep = 0;
#pragma unroll
    for (int g = 0; g < 32; ++g) {
        int v = src[g * 32 + lane];
        unsigned m = __ballot_sync(0xffffffffu, v > 0);
        if (g == lane) keep = m;
    }
    g_Ab[(size_t)warpId * 32 + lane] = keep;
}

// ---------------- K4: fused masked-softmax attention ---------------------
// CTA: (batch b, 64-row i-block), 128 threads; thread = (2 rows, 1 head).
// j streamed in chunks of 32, double-buffered shared with register prefetch.
// Accumulation via packed fma.rn.f32x2 (full fp32 rate on sm_103a).
__global__ __launch_bounds__(128) void k_attn(float* __restrict__ out) {
    constexpr int JC = 32;
    __shared__ float4 sWh[2][JC * 32];   // 16 KB per buffer, row j = 32 float4
    __shared__ float4 sJP[2][JC * HE];   // 2 KB per buffer

    int tid = threadIdx.x;
    int b = blockIdx.x >> 5;                 // N/64 = 32 i-blocks per batch
    int ibase = (blockIdx.x & 31) << 6;
    int h = tid & 3, il = tid >> 2;          // il in [0,32)
    int i0 = ibase + il * 2;
    size_t bn = (size_t)b * NN;

    float4 ip0 = g_ip[((bn + i0) << 2) + h];
    float4 ip1 = g_ip[((bn + i0 + 1) << 2) + h];
    const float4*   gWh = (const float4*)g_Wh + bn * 32;
    const float4*   gJP = g_jp + bn * 4;
    const unsigned* gA0 = g_Ab + (bn + i0) * 64;
    const unsigned* gA1 = gA0 + 64;

    unsigned long long acc0[16], acc1[16];
#pragma unroll
    for (int k = 0; k < 16; ++k) { acc0[k] = 0ull; acc1[k] = 0ull; }
    float z0 = 0.f, z1 = 0.f;

    // prime chunk 0
#pragma unroll
    for (int m = 0; m < 8; ++m) sWh[0][tid + 128 * m] = gWh[tid + 128 * m];
    sJP[0][tid] = gJP[tid];
    unsigned wa0 = gA0[0], wa1 = gA1[0];
    __syncthreads();

    for (int c = 0; c < NN / JC; ++c) {
        int cur = c & 1, nxt = cur ^ 1;
        float4 r[8], rj;
        unsigned na0 = 0, na1 = 0;
        bool more = (c + 1 < NN / JC);
        if (more) {       // prefetch next chunk into registers (hides L2 latency)
            const float4* src = gWh + (size_t)(c + 1) * JC * 32;
#pragma unroll
            for (int m = 0; m < 8; ++m) r[m] = src[tid + 128 * m];
            rj = gJP[(c + 1) * JC * 4 + tid];
            na0 = gA0[c + 1];
            na1 = gA1[c + 1];
        }

        int m0 = (int)__brev(wa0), m1 = (int)__brev(wa1);
        const float4* wbase = &sWh[cur][h * 8];
        const float4* jbase = &sJP[cur][h];

#pragma unroll 8
        for (int jj = 0; jj < JC; ++jj) {
            float4 jp = jbase[jj * 4];                       // {t_j, u_j, v_j, -}
            float p0 = (jp.x > ip0.x) ? ip0.y * jp.y : ip0.z * jp.z;
            float p1 = (jp.x > ip1.x) ? ip1.y * jp.y : ip1.z * jp.z;
            p0 = (m0 < 0) ? p0 : 0.0f;                       // adjacency bit (MSB-first)
            p1 = (m1 < 0) ? p1 : 0.0f;
            m0 <<= 1; m1 <<= 1;
            z0 += p0; z1 += p1;

            unsigned long long P0, P1;
            asm("mov.b64 %0, {%1, %1};" : "=l"(P0) : "f"(p0));
            asm("mov.b64 %0, {%1, %1};" : "=l"(P1) : "f"(p1));

            const float4* wrow = wbase + jj * 32;
#pragma unroll
            for (int k = 0; k < 8; ++k) {
                ulonglong2 w = *reinterpret_cast<const ulonglong2*>(wrow + k);
                asm("fma.rn.f32x2 %0, %1, %2, %0;" : "+l"(acc0[2 * k])     : "l"(w.x), "l"(P0));
                asm("fma.rn.f32x2 %0, %1, %2, %0;" : "+l"(acc0[2 * k + 1]) : "l"(w.y), "l"(P0));
                asm("fma.rn.f32x2 %0, %1, %2, %0;" : "+l"(acc1[2 * k])     : "l"(w.x), "l"(P1));
                asm("fma.rn.f32x2 %0, %1, %2, %0;" : "+l"(acc1[2 * k + 1]) : "l"(w.y), "l"(P1));
            }
        }

        if (more) {       // write prefetched data to the other buffer
#pragma unroll
            for (int m = 0; m < 8; ++m) sWh[nxt][tid + 128 * m] = r[m];
            sJP[nxt][tid] = rj;
        }
        wa0 = na0; wa1 = na1;
        __syncthreads();
    }

    // epilogue: divide by row sums, store fp32
    float rz0 = 1.0f / z0, rz1 = 1.0f / z1;
    float* o0 = out + (bn + i0) * 128 + h * 32;
    float* o1 = o0 + 128;
#pragma unroll
    for (int k = 0; k < 8; ++k) {
        float a0, a1, a2, a3;
        asm("mov.b64 {%0, %1}, %2;" : "=f"(a0), "=f"(a1) : "l"(acc0[2 * k]));
        asm("mov.b64 {%0, %1}, %2;" : "=f"(a2), "=f"(a3) : "l"(acc0[2 * k + 1]));
        ((float4*)o0)[k] = make_float4(a0 * rz0, a1 * rz0, a2 * rz0, a3 * rz0);
        asm("mov.b64 {%0, %1}, %2;" : "=f"(a0), "=f"(a1) : "l"(acc1[2 * k]));
        asm("mov.b64 {%0, %1}, %2;" : "=f"(a2), "=f"(a3) : "l"(acc1[2 * k + 1]));
        ((float4*)o1)[k] = make_float4(a0 * rz1, a1 * rz1, a2 * rz1, a3 * rz1);
    }
}

// ---------------- launch -------------------------------------------------
extern "C" void kernel_launch(void* const* d_in, const int* in_sizes, int n_in,
                              void* d_out, int out_size) {
    const float* h = nullptr;
    const int*   A = nullptr;
    const float* W = nullptr;
    const float* a = nullptr;
    // inputs are distinguishable by element count; robust to ordering
    for (int i = 0; i < n_in; ++i) {
        switch (in_sizes[i]) {
            case BB * NN * 128:      h = (const float*)d_in[i]; break;  // 2,097,152
            case 128 * 128:          W = (const float*)d_in[i]; break;  // 16,384
            case 2 * HD:             a = (const float*)d_in[i]; break;  // 64
            default:                 A = (const int*)d_in[i];   break;  // 33,554,432
        }
    }
    float* out = (float*)d_out;

    k_mm    <<<(BB * NN) / 64, 256>>>(h, W);
    k_params<<<(BB * NN * HE) / 256, 256>>>(a);
    k_pack  <<<4096, 256>>>(A);   // 4096*256 threads = 32768 warps * 1024 = B*N*N
    k_attn  <<<BB * (NN / 64), 128>>>(out);
}

// round 10
// speedup vs baseline: 3.4335x; 3.4335x over previous
#include <cuda_runtime.h>
#include <cstdint>
#include <cstddef>

#define BB 8
#define NN 2048
#define HE 4
#define HD 32

typedef unsigned long long ull;

// ---------------- device scratch ----------------
__device__ float    g_Wh[BB * NN * 128];            // 8 MB   [b*N+n][128]
__device__ float2   g_ip2[BB * NN * HE];            // 512KB  {e^s, e^{0.2s}}
__device__ float2   g_jp2[BB * NN * HE];            // 512KB  {e^t, e^{0.2t}}
__device__ unsigned g_Ab[BB * NN * (NN / 32)];      // 4 MB   packed adjacency bits

// ---------------- helpers ----------------
__device__ __forceinline__ ull packf2(float lo, float hi) {
    ull r; asm("mov.b64 %0,{%1,%2};" : "=l"(r) : "f"(lo), "f"(hi)); return r;
}
__device__ __forceinline__ void unpackf2(ull v, float& lo, float& hi) {
    asm("mov.b64 {%0,%1},%2;" : "=f"(lo), "=f"(hi) : "l"(v));
}

// ---------------- K1: Wh = h @ W  (16384x128 @ 128x128) ----------------
__global__ __launch_bounds__(256) void k_mm(const float* __restrict__ hmat,
                                            const float* __restrict__ W) {
    __shared__ float hs[64 * 36];
    __shared__ float Ws[32 * 128];
    int tid = threadIdx.x;
    int tx = tid & 15, ty = tid >> 4;
    int rbase = blockIdx.x * 64;

    float acc[4][8];
#pragma unroll
    for (int i = 0; i < 4; ++i)
#pragma unroll
        for (int j = 0; j < 8; ++j) acc[i][j] = 0.f;

    for (int k0 = 0; k0 < 128; k0 += 32) {
        __syncthreads();
#pragma unroll
        for (int m = 0; m < 2; ++m) {
            int idx = tid * 2 + m;
            int r = idx >> 3, q = idx & 7;
            *(float4*)(hs + r * 36 + q * 4) =
                *(const float4*)(hmat + (size_t)(rbase + r) * 128 + k0 + q * 4);
        }
#pragma unroll
        for (int m = 0; m < 4; ++m) {
            int idx = tid + 256 * m;
            int kk = idx >> 5, c4 = idx & 31;
            *(float4*)(Ws + kk * 128 + c4 * 4) =
                *(const float4*)(W + (size_t)(k0 + kk) * 128 + c4 * 4);
        }
        __syncthreads();
#pragma unroll
        for (int kk = 0; kk < 32; ++kk) {
            float av[4], bv[8];
#pragma unroll
            for (int i = 0; i < 4; ++i) av[i] = hs[(ty * 4 + i) * 36 + kk];
#pragma unroll
            for (int j = 0; j < 8; ++j) bv[j] = Ws[kk * 128 + tx + 16 * j];
#pragma unroll
            for (int i = 0; i < 4; ++i)
#pragma unroll
                for (int j = 0; j < 8; ++j) acc[i][j] += av[i] * bv[j];
        }
    }
#pragma unroll
    for (int i = 0; i < 4; ++i)
#pragma unroll
        for (int j = 0; j < 8; ++j)
            g_Wh[(size_t)(rbase + ty * 4 + i) * 128 + tx + 16 * j] = acc[i][j];
}

// ---------------- K2: per-(node,head) attention params -------------------
// exp(leakyrelu(s_i+t_j)) = max(e^{s+t}, e^{0.2(s+t)}) = max(e^s e^t, e^{0.2s} e^{0.2t})
__global__ __launch_bounds__(256) void k_params(const float* __restrict__ a) {
    __shared__ float sa[64];
    int tid = threadIdx.x;
    if (tid < 64) sa[tid] = a[tid];
    __syncthreads();
    int idx = blockIdx.x * 256 + tid;           // = (b*N+n)*4 + h
    int nh = idx >> 2, hh = idx & 3;
    const float4* wh = (const float4*)(g_Wh + (size_t)nh * 128 + hh * 32);
    float s = 0.f, t = 0.f;
#pragma unroll
    for (int k = 0; k < 8; ++k) {
        float4 w = wh[k];
        s += w.x * sa[4 * k + 0] + w.y * sa[4 * k + 1] + w.z * sa[4 * k + 2] + w.w * sa[4 * k + 3];
        t += w.x * sa[32 + 4 * k + 0] + w.y * sa[32 + 4 * k + 1] + w.z * sa[32 + 4 * k + 2] + w.w * sa[32 + 4 * k + 3];
    }
    g_ip2[idx] = make_float2(expf(s), expf(0.2f * s));
    g_jp2[idx] = make_float2(expf(t), expf(0.2f * t));
}

// ---------------- K3: pack A into bitmasks ----------------
__global__ __launch_bounds__(256) void k_pack(const int* __restrict__ A) {
    int gt = blockIdx.x * 256 + threadIdx.x;
    int warpId = gt >> 5, lane = gt & 31;
    const int* src = A + (size_t)warpId * 1024;
    unsigned keep = 0;
#pragma unroll
    for (int g = 0; g < 32; ++g) {
        int v = src[g * 32 + lane];
        unsigned m = __ballot_sync(0xffffffffu, v > 0);
        if (g == lane) keep = m;
    }
    g_Ab[(size_t)warpId * 32 + lane] = keep;
}

// ---------------- K4: fused masked-softmax attention ---------------------
// CTA: (batch, 32-row block), 128 threads, grid 512, 4 CTAs/SM.
// thread = 2 rows x 16 dims (one head-half). Warp = 16 row-pairs x 1 head-half
//   -> Wh LDS.128 has 2 distinct addrs/warp (16-lane broadcast, conflict-free),
//      jp LDS is warp-uniform.
// Staging: LDG->reg->STS double buffer (round-8 proven), one barrier per chunk.
// Masks: round-8 proven prefetch + __brev + sign-bit walk.
__global__ __launch_bounds__(128, 4) void k_attn(float* __restrict__ out) {
    constexpr int JC = 32;
    __shared__ float  sWh[2][JC * 128];     // 16 KB per buffer
    __shared__ float2 sJP[2][JC * HE];      // 1 KB per buffer

    int tid = threadIdx.x;
    int b = blockIdx.x >> 6;                  // 64 i-blocks of 32 rows
    int ibase = (blockIdx.x & 63) << 5;
    int il = tid & 15, hh = tid >> 4;         // hh 0..7
    int h = hh >> 1, half = hh & 1;
    int i0 = ibase + il * 2;
    int dimoff = h * 32 + half * 16;          // float offset within 128-dim row
    size_t bn = (size_t)b * NN;

    float2 e0 = g_ip2[(bn + i0) * 4 + h];         // {E1, E2} row i0
    float2 e1 = g_ip2[(bn + i0 + 1) * 4 + h];     // {E1, E2} row i0+1

    const float4*   gWh4 = (const float4*)(g_Wh + bn * 128);
    const float2*   gJP  = g_jp2 + bn * 4;
    const unsigned* gA0  = g_Ab + (bn + i0) * 64;
    const unsigned* gA1  = gA0 + 64;

    ull acc[2][8];
#pragma unroll
    for (int r = 0; r < 2; ++r)
#pragma unroll
        for (int k = 0; k < 8; ++k) acc[r][k] = 0ull;
    float z0 = 0.f, z1 = 0.f;

    // prime chunk 0 (32 nodes x 128 dims = 1024 float4; 8 per thread)
#pragma unroll
    for (int m = 0; m < 8; ++m)
        ((float4*)sWh[0])[tid + 128 * m] = gWh4[tid + 128 * m];
    sJP[0][tid] = gJP[tid];
    unsigned wa0 = gA0[0], wa1 = gA1[0];
    __syncthreads();

    for (int c = 0; c < NN / JC; ++c) {
        int cur = c & 1, nxt = cur ^ 1;
        float4 r[8]; float2 rj;
        unsigned na0 = 0, na1 = 0;
        bool more = (c + 1 < NN / JC);
        if (more) {   // prefetch next chunk into registers (hides L2 latency)
            const float4* src = gWh4 + (size_t)(c + 1) * JC * 32;
#pragma unroll
            for (int m = 0; m < 8; ++m) r[m] = src[tid + 128 * m];
            rj  = gJP[(c + 1) * JC * 4 + tid];
            na0 = gA0[c + 1];
            na1 = gA1[c + 1];
        }

        int m0 = (int)__brev(wa0), m1 = (int)__brev(wa1);
        const float*  whc = sWh[cur];
        const float2* jpc = sJP[cur];

#pragma unroll 4
        for (int jj = 0; jj < JC; ++jj) {
            float2 jp = jpc[jj * 4 + h];                 // {u_j, v_j}
            float p0 = fmaxf(e0.x * jp.x, e0.y * jp.y);  // exp(leakyrelu(s+t))
            float p1 = fmaxf(e1.x * jp.x, e1.y * jp.y);
            p0 = (m0 < 0) ? p0 : 0.0f;                   // adjacency bit (MSB-first)
            p1 = (m1 < 0) ? p1 : 0.0f;
            m0 <<= 1; m1 <<= 1;
            z0 += p0; z1 += p1;

            ull P0 = packf2(p0, p0);
            ull P1 = packf2(p1, p1);

            const float4* wr = (const float4*)&whc[jj * 128 + dimoff];
#pragma unroll
            for (int k = 0; k < 4; ++k) {
                ulonglong2 w = *reinterpret_cast<const ulonglong2*>(wr + k);
                asm("fma.rn.f32x2 %0, %1, %2, %0;" : "+l"(acc[0][2 * k])     : "l"(w.x), "l"(P0));
                asm("fma.rn.f32x2 %0, %1, %2, %0;" : "+l"(acc[0][2 * k + 1]) : "l"(w.y), "l"(P0));
                asm("fma.rn.f32x2 %0, %1, %2, %0;" : "+l"(acc[1][2 * k])     : "l"(w.x), "l"(P1));
                asm("fma.rn.f32x2 %0, %1, %2, %0;" : "+l"(acc[1][2 * k + 1]) : "l"(w.y), "l"(P1));
            }
        }

        if (more) {   // write prefetched data into the other buffer
#pragma unroll
            for (int m = 0; m < 8; ++m)
                ((float4*)sWh[nxt])[tid + 128 * m] = r[m];
            sJP[nxt][tid] = rj;
        }
        wa0 = na0; wa1 = na1;
        __syncthreads();
    }

    // epilogue: divide by row sums, store fp32
    float rz0 = 1.0f / z0, rz1 = 1.0f / z1;
#pragma unroll
    for (int r = 0; r < 2; ++r) {
        float rz = r ? rz1 : rz0;
        float* o = out + (bn + i0 + r) * 128 + dimoff;
#pragma unroll
        for (int k = 0; k < 4; ++k) {
            float a0, a1, a2, a3;
            unpackf2(acc[r][2 * k],     a0, a1);
            unpackf2(acc[r][2 * k + 1], a2, a3);
            ((float4*)o)[k] = make_float4(a0 * rz, a1 * rz, a2 * rz, a3 * rz);
        }
    }
}

// ---------------- launch -------------------------------------------------
extern "C" void kernel_launch(void* const* d_in, const int* in_sizes, int n_in,
                              void* d_out, int out_size) {
    const float* h = nullptr;
    const int*   A = nullptr;
    const float* W = nullptr;
    const float* a = nullptr;
    for (int i = 0; i < n_in; ++i) {
        switch (in_sizes[i]) {
            case BB * NN * 128:      h = (const float*)d_in[i]; break;
            case 128 * 128:          W = (const float*)d_in[i]; break;
            case 2 * HD:             a = (const float*)d_in[i]; break;
            default:                 A = (const int*)d_in[i];   break;
        }
    }
    float* out = (float*)d_out;

    k_mm    <<<(BB * NN) / 64, 256>>>(h, W);
    k_params<<<(BB * NN * HE) / 256, 256>>>(a);
    k_pack  <<<4096, 256>>>(A);
    k_attn  <<<BB * (NN / 32), 128>>>(out);
}